// round 11
// baseline (speedup 1.0000x reference)
#include <cuda_runtime.h>
#include <cuda_fp16.h>
#include <cstdint>

#define H_    320
#define E_    640
#define B_    32
#define T_    2000
#define KCONV 100
#define NF_   10
#define PAD_  50
#define M_    (B_*T_)      // 64000
#define NB_   5            // N blocks of 128
#define NKC   10           // K chunks of 64
#define BM 128
#define BN 128
#define KC 64
#define GZ 40              // gpart t-splits (T_/GZ = 50)

// ---- scratch (device globals) ----
__device__ float g_q[B_*E_];
__device__ float g_f[M_*NF_];
__device__ float g_epart[M_*NB_];
__device__ float g_gpart[GZ*B_*E_];
__device__ __align__(256) __half g_Ah[(size_t)M_*E_];
__device__ __align__(256) __half g_Bh[(size_t)E_*E_];   // transposed [n][k]

// ---------------- helpers ----------------
__device__ __forceinline__ uint32_t s2u(const void* p) {
    return (uint32_t)__cvta_generic_to_shared(p);
}
__device__ __forceinline__ uint32_t swz(uint32_t o) { return o ^ ((o >> 3) & 0x70); }

__device__ __forceinline__ void cp16(uint32_t dst, const void* src) {
    asm volatile("cp.async.cg.shared.global [%0], [%1], 16;" :: "r"(dst), "l"(src));
}
__device__ __forceinline__ void cp_commit() { asm volatile("cp.async.commit_group;"); }

__device__ __forceinline__ void ldsm_x4(uint32_t* r, uint32_t addr) {
    asm volatile("ldmatrix.sync.aligned.m8n8.x4.shared.b16 {%0,%1,%2,%3}, [%4];"
                 : "=r"(r[0]), "=r"(r[1]), "=r"(r[2]), "=r"(r[3]) : "r"(addr));
}
__device__ __forceinline__ void mma16816(float* d, const uint32_t* a, const uint32_t* b) {
    asm volatile("mma.sync.aligned.m16n8k16.row.col.f32.f16.f16.f32 "
                 "{%0,%1,%2,%3},{%4,%5,%6,%7},{%8,%9},{%0,%1,%2,%3};"
                 : "+f"(d[0]), "+f"(d[1]), "+f"(d[2]), "+f"(d[3])
                 : "r"(a[0]), "r"(a[1]), "r"(a[2]), "r"(a[3]), "r"(b[0]), "r"(b[1]));
}
__device__ __forceinline__ uint32_t pack2h(float a, float b) {
    __half2 h = __floats2half2_rn(a, b);
    return *reinterpret_cast<uint32_t*>(&h);
}

// tanh(x) = 1 - 2/(exp(2x)+1) via MUFU.EX2 + MUFU.RCP (rel err ~1e-6)
__device__ __forceinline__ float fast_tanh(float x) {
    float e;
    asm("ex2.approx.f32 %0, %1;" : "=f"(e) : "f"(x * 2.8853900817779268f));
    float r;
    asm("rcp.approx.f32 %0, %1;" : "=f"(r) : "f"(e + 1.0f));
    return 1.0f - 2.0f * r;
}

// ---------------------------------------------------------------------------
// mega prep (one launch):
//   [0,10000)      prepA  h fp32 -> fp16
//   [10000,11600)  prepB  W_he -> [n][k] fp16
//   [11600,11632)  q
//   [11632,12144)  conv
// ---------------------------------------------------------------------------
__global__ void k_prep(const float* __restrict__ hb, const float* __restrict__ W_he,
                       const float* __restrict__ s, const float* __restrict__ W_se,
                       const float* __restrict__ b_se, const float* __restrict__ b_he,
                       const float* __restrict__ b_fe,
                       const float* __restrict__ alpha, const float* __restrict__ conv_w) {
    __shared__ float sbuf[868];
    int bid = blockIdx.x, tid = threadIdx.x;

    if (bid < 10000) {                      // ---- prepA
        size_t base = ((size_t)bid * 256 + tid) * 4;
        #pragma unroll
        for (int it = 0; it < 4; it++) {
            float4 v = reinterpret_cast<const float4*>(hb)[base + it];
            uint2 hh = { pack2h(v.x, v.y), pack2h(v.z, v.w) };
            reinterpret_cast<uint2*>(g_Ah)[base + it] = hh;
        }
        return;
    }
    if (bid < 11600) {                      // ---- prepB
        int idx = (bid - 10000) * 256 + tid;
        int k = idx / E_, n = idx % E_;
        g_Bh[(size_t)n * E_ + k] = __float2half_rn(W_he[(size_t)k * E_ + n]);
        return;
    }
    if (bid < 11632) {                      // ---- q
        int b = bid - 11600;
        float* ss = sbuf;
        for (int i = tid; i < H_; i += 256) ss[i] = s[b*H_ + i];
        __syncthreads();
        for (int j = tid; j < E_; j += 256) {
            float acc = b_se[j] + b_he[j] + b_fe[j];
            #pragma unroll 4
            for (int k = 0; k < H_; k++) acc += ss[k] * W_se[k*E_ + j];
            g_q[b*E_ + j] = acc;
        }
        return;
    }
    // ---- conv
    int c  = bid - 11632;                   // [0,512)
    int b  = c >> 4;
    int by = (c & 15) >> 1;
    int ob = (c & 1) * 5;
    int t0 = by * 256;
    float* a_s = sbuf;
    float* w_s = sbuf + 356;
    for (int i = tid; i < 5*KCONV; i += 256) w_s[i] = conv_w[ob*KCONV + i];
    for (int i = tid; i < 256 + KCONV - 1; i += 256) {
        int idx = t0 - PAD_ + i;
        a_s[i] = (idx >= 0 && idx < T_) ? alpha[b*T_ + idx] : 0.f;
    }
    __syncthreads();
    int t = t0 + tid;
    if (t >= T_) return;
    float acc[5];
    #pragma unroll
    for (int o = 0; o < 5; o++) acc[o] = 0.f;
    #pragma unroll 4
    for (int k = 0; k < KCONV; k++) {
        float av = a_s[tid + k];
        #pragma unroll
        for (int o = 0; o < 5; o++) acc[o] += av * w_s[o*KCONV + k];
    }
    int m = b*T_ + t;
    #pragma unroll
    for (int o = 0; o < 5; o++) g_f[m*NF_ + ob + o] = acc[o];
}

// ---------------------------------------------------------------------------
// Energy GEMM (R7-exact): fp16 mma.sync, 2-stage cp.async, fused epilogue.
// Grid (NB_, 500), 256 threads, 2 CTAs/SM. dyn smem 64KB.
// ---------------------------------------------------------------------------
__global__ void __launch_bounds__(256, 2) k_energy(
    const float* __restrict__ W_fe, const float* __restrict__ W_ee) {

    extern __shared__ unsigned char dyn[];
    __shared__ float f_s[BM][NF_];
    __shared__ float wfe_s[NF_][BN];
    __shared__ float wee_s[BN];
    __shared__ float ep_s[BM][4];

    const int tid = threadIdx.x;
    const int nb = blockIdx.x, mt = blockIdx.y;
    const int n0 = nb * BN, m0 = mt * BM;
    const uint32_t smem0 = s2u(dyn);

    // epilogue constants
    for (int i = tid; i < NF_*BN; i += 256) {
        int o = i >> 7, j = i & 127;
        wfe_s[o][j] = W_fe[o*E_ + n0 + j];
    }
    if (tid < BN) wee_s[tid] = W_ee[n0 + tid];
    for (int i = tid; i < BM*NF_; i += 256) {
        int r = i / NF_, o = i % NF_;
        f_s[r][o] = g_f[(size_t)(m0 + r)*NF_ + o];
    }

    // ---- load machinery ----
    const int lr   = tid >> 1;
    const int segb = (tid & 1) * 4;
    const __half* pAh = g_Ah + (size_t)(m0 + lr)*E_;
    const __half* pBh = g_Bh + (size_t)(n0 + lr)*E_;

    auto load_stage = [&](int kc, int st) {
        uint32_t base = smem0 + st * 32768;
        int koff = kc * KC;
        #pragma unroll
        for (int i = 0; i < 4; i++) {
            int seg = segb + i;
            uint32_t so = swz((uint32_t)lr*128 + seg*16);
            cp16(base +         so, pAh + koff + seg*8);
            cp16(base + 16384 + so, pBh + koff + seg*8);
        }
        cp_commit();
    };

    // ---- mma machinery ----
    const int wid = tid >> 5, lane = tid & 31;
    const int warp_m = wid & 1, warp_n = wid >> 1;
    const int g = lane >> 3, l = lane & 7;
    const int a_row = l + (g & 1)*8, a_col = (g >> 1)*16;
    const int b_row = l + (g >> 1)*8, b_col = (g & 1)*16;

    float acc[4][4][4];
    #pragma unroll
    for (int mi = 0; mi < 4; mi++)
        #pragma unroll
        for (int ni = 0; ni < 4; ni++)
            #pragma unroll
            for (int r = 0; r < 4; r++) acc[mi][ni][r] = 0.f;

    auto compute_stage = [&](int st) {
        uint32_t sAh = smem0 + st*32768;
        uint32_t sBh = sAh + 16384;
        #pragma unroll
        for (int ks = 0; ks < 4; ks++) {
            uint32_t ah[4][4], bh[2][4];
            #pragma unroll
            for (int mi = 0; mi < 4; mi++) {
                uint32_t off = swz((uint32_t)(warp_m*64 + mi*16 + a_row)*128 + ks*32 + a_col);
                ldsm_x4(ah[mi], sAh + off);
            }
            #pragma unroll
            for (int nj = 0; nj < 2; nj++) {
                uint32_t off = swz((uint32_t)(warp_n*32 + nj*16 + b_row)*128 + ks*32 + b_col);
                ldsm_x4(bh[nj], sBh + off);
            }
            #pragma unroll
            for (int mi = 0; mi < 4; mi++)
                #pragma unroll
                for (int ni = 0; ni < 4; ni++)
                    mma16816(acc[mi][ni], ah[mi], &bh[ni >> 1][(ni & 1)*2]);
        }
    };

    // ---- 2-stage pipeline ----
    load_stage(0, 0);
    for (int kc = 0; kc < NKC; kc++) {
        if (kc < NKC - 1) load_stage(kc + 1, (kc + 1) & 1);
        if (kc < NKC - 1) asm volatile("cp.async.wait_group 1;");
        else              asm volatile("cp.async.wait_group 0;");
        __syncthreads();
        compute_stage(kc & 1);
        __syncthreads();
    }

    // ---- epilogue ----
    const int r4 = lane >> 2, cp2 = (lane & 3)*2;
    #pragma unroll
    for (int mi = 0; mi < 4; mi++) {
        #pragma unroll
        for (int half = 0; half < 2; half++) {
            int m_local = warp_m*64 + mi*16 + half*8 + r4;
            int m = m0 + m_local;
            int b = m / T_;
            const float* qp = g_q + (size_t)b*E_ + n0;
            float partial = 0.f;
            #pragma unroll
            for (int ni = 0; ni < 4; ni++) {
                #pragma unroll
                for (int c = 0; c < 2; c++) {
                    int nl = warp_n*32 + ni*8 + cp2 + c;
                    float v = acc[mi][ni][half*2 + c] + qp[nl];
                    #pragma unroll
                    for (int o = 0; o < NF_; o++) v += f_s[m_local][o] * wfe_s[o][nl];
                    partial += fast_tanh(v) * wee_s[nl];
                }
            }
            partial += __shfl_xor_sync(0xffffffffu, partial, 1);
            partial += __shfl_xor_sync(0xffffffffu, partial, 2);
            if ((lane & 3) == 0) ep_s[m_local][warp_n] = partial;
        }
    }
    __syncthreads();
    if (tid < BM) {
        float ssum = ep_s[tid][0] + ep_s[tid][1] + ep_s[tid][2] + ep_s[tid][3];
        g_epart[(size_t)(m0 + tid)*NB_ + nb] = ssum;
    }
}

// ---------------------------------------------------------------------------
// softmax over T per batch (1024 threads)
// ---------------------------------------------------------------------------
__global__ void k_softmax(float* __restrict__ alpha_out) {
    int b = blockIdx.x;
    int tid = threadIdx.x;
    __shared__ float es[T_];
    __shared__ float red[1024];

    float lmax = -1e30f;
    for (int t = tid; t < T_; t += 1024) {
        float v = 0.f;
        #pragma unroll
        for (int nb = 0; nb < NB_; nb++) v += g_epart[(size_t)(b*T_ + t)*NB_ + nb];
        es[t] = v;
        lmax = fmaxf(lmax, v);
    }
    red[tid] = lmax;
    __syncthreads();
    for (int s = 512; s > 0; s >>= 1) {
        if (tid < s) red[tid] = fmaxf(red[tid], red[tid + s]);
        __syncthreads();
    }
    float mx = red[0];
    __syncthreads();

    float lsum = 0.f;
    for (int t = tid; t < T_; t += 1024) {
        float ev = expf(es[t] - mx);
        es[t] = ev;
        lsum += ev;
    }
    red[tid] = lsum;
    __syncthreads();
    for (int s = 512; s > 0; s >>= 1) {
        if (tid < s) red[tid] += red[tid + s];
        __syncthreads();
    }
    float inv = 1.f / red[0];
    __syncthreads();
    for (int t = tid; t < T_; t += 1024) alpha_out[b*T_ + t] = es[t] * inv;
}

// ---------------------------------------------------------------------------
// context g: 320 threads, one half2 per thread; grid (B, 1, GZ=40).
// t-chunk = 50; fully coalesced 1280B lines per t.
// ---------------------------------------------------------------------------
__global__ void __launch_bounds__(320) k_gpart(const float* __restrict__ alpha_out) {
    int b = blockIdx.x, z = blockIdx.z;
    int t0 = z * (T_/GZ);
    int p = threadIdx.x;                    // e-pair 0..319
    const __half2* hp = reinterpret_cast<const __half2*>(g_Ah + (size_t)b*T_*E_) + p;
    const float* ap = alpha_out + b*T_;
    float accx = 0.f, accy = 0.f;
    #pragma unroll 5
    for (int t = t0; t < t0 + T_/GZ; t++) {
        __half2 v = __ldg(hp + (size_t)t*(E_/2));
        float2 f = __half22float2(v);
        float a = __ldg(ap + t);
        accx += a * f.x;
        accy += a * f.y;
    }
    float* gp = g_gpart + (size_t)(z*B_ + b)*E_ + p*2;
    gp[0] = accx;
    gp[1] = accy;
}

__global__ void k_greduce(float* __restrict__ g_out) {
    int i = blockIdx.x*256 + threadIdx.x;
    if (i < B_*E_) {
        float s = 0.f;
        #pragma unroll
        for (int z = 0; z < GZ; z++) s += g_gpart[(size_t)z*(B_*E_) + i];
        g_out[i] = s;
    }
}

// ---------------------------------------------------------------------------
extern "C" void kernel_launch(void* const* d_in, const int* in_sizes, int n_in,
                              void* d_out, int out_size) {
    const float* s      = (const float*)d_in[0];
    const float* hb     = (const float*)d_in[1];
    const float* alpha  = (const float*)d_in[2];
    const float* W_se   = (const float*)d_in[4];
    const float* b_se   = (const float*)d_in[5];
    const float* W_he   = (const float*)d_in[6];
    const float* b_he   = (const float*)d_in[7];
    const float* W_fe   = (const float*)d_in[8];
    const float* b_fe   = (const float*)d_in[9];
    const float* W_ee   = (const float*)d_in[10];
    const float* conv_w = (const float*)d_in[12];

    float* out       = (float*)d_out;
    float* g_out     = out;            // [B, E]
    float* alpha_out = out + B_*E_;    // [B, T]

    cudaFuncSetAttribute(k_energy, cudaFuncAttributeMaxDynamicSharedMemorySize, 65536);

    k_prep<<<12144, 256>>>(hb, W_he, s, W_se, b_se, b_he, b_fe, alpha, conv_w);
    k_energy<<<dim3(NB_, M_/BM), 256, 65536>>>(W_fe, W_ee);
    k_softmax<<<B_, 1024>>>(alpha_out);
    k_gpart<<<dim3(B_, 1, GZ), 320>>>(alpha_out);
    k_greduce<<<(B_*E_ + 255)/256, 256>>>(g_out);
}

// round 13
// speedup vs baseline: 1.3890x; 1.3890x over previous
#include <cuda_runtime.h>
#include <cuda_fp16.h>
#include <cstdint>

#define H_    320
#define E_    640
#define B_    32
#define T_    2000
#define KCONV 100
#define NF_   10
#define PAD_  50
#define M_    (B_*T_)      // 64000
#define NB_   5            // N blocks of 128
#define NKC   10           // K chunks of 64
#define BM 128
#define BN 128
#define KC 64
#define NST 3              // pipeline stages (R8 measured-best)
#define GZ 20              // gpart z-splits (x4 sub-slices = 80 partials)

// ---- scratch (device globals) ----
__device__ float g_q[B_*E_];
__device__ float g_f[M_*NF_];
__device__ float g_epart[M_*NB_];
__device__ float g_gpart[(GZ*4)*B_*E_];
__device__ __align__(256) __half g_Ah[(size_t)M_*E_];
__device__ __align__(256) __half g_Bh[(size_t)E_*E_];   // transposed [n][k]

// ---------------- helpers ----------------
__device__ __forceinline__ uint32_t s2u(const void* p) {
    return (uint32_t)__cvta_generic_to_shared(p);
}
__device__ __forceinline__ uint32_t swz(uint32_t o) { return o ^ ((o >> 3) & 0x70); }

__device__ __forceinline__ void cp16(uint32_t dst, const void* src) {
    asm volatile("cp.async.cg.shared.global [%0], [%1], 16;" :: "r"(dst), "l"(src));
}
__device__ __forceinline__ void cp_commit() { asm volatile("cp.async.commit_group;"); }

__device__ __forceinline__ void ldsm_x4(uint32_t* r, uint32_t addr) {
    asm volatile("ldmatrix.sync.aligned.m8n8.x4.shared.b16 {%0,%1,%2,%3}, [%4];"
                 : "=r"(r[0]), "=r"(r[1]), "=r"(r[2]), "=r"(r[3]) : "r"(addr));
}
__device__ __forceinline__ void mma16816(float* d, const uint32_t* a, const uint32_t* b) {
    asm volatile("mma.sync.aligned.m16n8k16.row.col.f32.f16.f16.f32 "
                 "{%0,%1,%2,%3},{%4,%5,%6,%7},{%8,%9},{%0,%1,%2,%3};"
                 : "+f"(d[0]), "+f"(d[1]), "+f"(d[2]), "+f"(d[3])
                 : "r"(a[0]), "r"(a[1]), "r"(a[2]), "r"(a[3]), "r"(b[0]), "r"(b[1]));
}
__device__ __forceinline__ uint32_t pack2h(float a, float b) {
    __half2 h = __floats2half2_rn(a, b);
    return *reinterpret_cast<uint32_t*>(&h);
}

// tanh(x) = 1 - 2/(exp(2x)+1) via MUFU.EX2 + MUFU.RCP (rel err ~1e-6)
__device__ __forceinline__ float fast_tanh(float x) {
    float e;
    asm("ex2.approx.f32 %0, %1;" : "=f"(e) : "f"(x * 2.8853900817779268f));
    float r;
    asm("rcp.approx.f32 %0, %1;" : "=f"(r) : "f"(e + 1.0f));
    return 1.0f - 2.0f * r;
}

// ---------------------------------------------------------------------------
// mega prep (one launch):
//   [0,10000)      prepA  h fp32 -> fp16
//   [10000,11600)  prepB  W_he -> [n][k] fp16
//   [11600,11632)  q
//   [11632,12144)  conv
// ---------------------------------------------------------------------------
__global__ void k_prep(const float* __restrict__ hb, const float* __restrict__ W_he,
                       const float* __restrict__ s, const float* __restrict__ W_se,
                       const float* __restrict__ b_se, const float* __restrict__ b_he,
                       const float* __restrict__ b_fe,
                       const float* __restrict__ alpha, const float* __restrict__ conv_w) {
    __shared__ float sbuf[868];
    int bid = blockIdx.x, tid = threadIdx.x;

    if (bid < 10000) {                      // ---- prepA
        size_t base = ((size_t)bid * 256 + tid) * 4;
        #pragma unroll
        for (int it = 0; it < 4; it++) {
            float4 v = reinterpret_cast<const float4*>(hb)[base + it];
            uint2 hh = { pack2h(v.x, v.y), pack2h(v.z, v.w) };
            reinterpret_cast<uint2*>(g_Ah)[base + it] = hh;
        }
        return;
    }
    if (bid < 11600) {                      // ---- prepB
        int idx = (bid - 10000) * 256 + tid;
        int k = idx / E_, n = idx % E_;
        g_Bh[(size_t)n * E_ + k] = __float2half_rn(W_he[(size_t)k * E_ + n]);
        return;
    }
    if (bid < 11632) {                      // ---- q
        int b = bid - 11600;
        float* ss = sbuf;
        for (int i = tid; i < H_; i += 256) ss[i] = s[b*H_ + i];
        __syncthreads();
        for (int j = tid; j < E_; j += 256) {
            float acc = b_se[j] + b_he[j] + b_fe[j];
            #pragma unroll 4
            for (int k = 0; k < H_; k++) acc += ss[k] * W_se[k*E_ + j];
            g_q[b*E_ + j] = acc;
        }
        return;
    }
    // ---- conv
    int c  = bid - 11632;                   // [0,512)
    int b  = c >> 4;
    int by = (c & 15) >> 1;
    int ob = (c & 1) * 5;
    int t0 = by * 256;
    float* a_s = sbuf;
    float* w_s = sbuf + 356;
    for (int i = tid; i < 5*KCONV; i += 256) w_s[i] = conv_w[ob*KCONV + i];
    for (int i = tid; i < 256 + KCONV - 1; i += 256) {
        int idx = t0 - PAD_ + i;
        a_s[i] = (idx >= 0 && idx < T_) ? alpha[b*T_ + idx] : 0.f;
    }
    __syncthreads();
    int t = t0 + tid;
    if (t >= T_) return;
    float acc[5];
    #pragma unroll
    for (int o = 0; o < 5; o++) acc[o] = 0.f;
    #pragma unroll 4
    for (int k = 0; k < KCONV; k++) {
        float av = a_s[tid + k];
        #pragma unroll
        for (int o = 0; o < 5; o++) acc[o] += av * w_s[o*KCONV + k];
    }
    int m = b*T_ + t;
    #pragma unroll
    for (int o = 0; o < 5; o++) g_f[m*NF_ + ob + o] = acc[o];
}

// ---------------------------------------------------------------------------
// Energy GEMM (R8-exact): fp16 mma.sync, 3-stage cp.async, one sync/iter.
// Grid (NB_, 500), 256 threads, 2 CTAs/SM. dyn smem: 3 x 32KB = 96KB.
// ---------------------------------------------------------------------------
__global__ void __launch_bounds__(256, 2) k_energy(
    const float* __restrict__ W_fe, const float* __restrict__ W_ee) {

    extern __shared__ unsigned char dyn[];
    __shared__ float f_s[BM][NF_];
    __shared__ float wfe_s[NF_][BN];
    __shared__ float wee_s[BN];
    __shared__ float ep_s[BM][4];

    const int tid = threadIdx.x;
    const int nb = blockIdx.x, mt = blockIdx.y;
    const int n0 = nb * BN, m0 = mt * BM;
    const uint32_t smem0 = s2u(dyn);

    // epilogue constants (overlaps with prologue loads)
    for (int i = tid; i < NF_*BN; i += 256) {
        int o = i >> 7, j = i & 127;
        wfe_s[o][j] = W_fe[o*E_ + n0 + j];
    }
    if (tid < BN) wee_s[tid] = W_ee[n0 + tid];
    for (int i = tid; i < BM*NF_; i += 256) {
        int r = i / NF_, o = i % NF_;
        f_s[r][o] = g_f[(size_t)(m0 + r)*NF_ + o];
    }

    // ---- load machinery ----
    const int lr   = tid >> 1;
    const int segb = (tid & 1) * 4;
    const __half* pAh = g_Ah + (size_t)(m0 + lr)*E_;
    const __half* pBh = g_Bh + (size_t)(n0 + lr)*E_;

    auto load_stage = [&](int kc, int st) {
        uint32_t base = smem0 + st * 32768;
        int koff = kc * KC;
        #pragma unroll
        for (int i = 0; i < 4; i++) {
            int seg = segb + i;
            uint32_t so = swz((uint32_t)lr*128 + seg*16);
            cp16(base +         so, pAh + koff + seg*8);
            cp16(base + 16384 + so, pBh + koff + seg*8);
        }
        cp_commit();
    };

    // ---- mma machinery ----
    const int wid = tid >> 5, lane = tid & 31;
    const int warp_m = wid & 1, warp_n = wid >> 1;
    const int g = lane >> 3, l = lane & 7;
    const int a_row = l + (g & 1)*8, a_col = (g >> 1)*16;
    const int b_row = l + (g >> 1)*8, b_col = (g & 1)*16;

    float acc[4][4][4];
    #pragma unroll
    for (int mi = 0; mi < 4; mi++)
        #pragma unroll
        for (int ni = 0; ni < 4; ni++)
            #pragma unroll
            for (int r = 0; r < 4; r++) acc[mi][ni][r] = 0.f;

    auto compute_stage = [&](int st) {
        uint32_t sAh = smem0 + st*32768;
        uint32_t sBh = sAh + 16384;
        #pragma unroll
        for (int ks = 0; ks < 4; ks++) {
            uint32_t ah[4][4], bh[2][4];
            #pragma unroll
            for (int mi = 0; mi < 4; mi++) {
                uint32_t off = swz((uint32_t)(warp_m*64 + mi*16 + a_row)*128 + ks*32 + a_col);
                ldsm_x4(ah[mi], sAh + off);
            }
            #pragma unroll
            for (int nj = 0; nj < 2; nj++) {
                uint32_t off = swz((uint32_t)(warp_n*32 + nj*16 + b_row)*128 + ks*32 + b_col);
                ldsm_x4(bh[nj], sBh + off);
            }
            #pragma unroll
            for (int mi = 0; mi < 4; mi++)
                #pragma unroll
                for (int ni = 0; ni < 4; ni++)
                    mma16816(acc[mi][ni], ah[mi], &bh[ni >> 1][(ni & 1)*2]);
        }
    };

    // ---- 3-stage pipeline, one sync per iteration ----
    load_stage(0, 0);
    load_stage(1, 1);
    asm volatile("cp.async.wait_group 1;");
    __syncthreads();

    for (int kc = 0; kc < NKC; kc++) {
        if (kc + 2 < NKC) load_stage(kc + 2, (kc + 2) % NST);
        compute_stage(kc % NST);
        if (kc + 1 < NKC) {
            if (kc + 2 < NKC) asm volatile("cp.async.wait_group 1;");
            else              asm volatile("cp.async.wait_group 0;");
        }
        __syncthreads();
    }

    // ---- epilogue ----
    const int r4 = lane >> 2, cp2 = (lane & 3)*2;
    #pragma unroll
    for (int mi = 0; mi < 4; mi++) {
        #pragma unroll
        for (int half = 0; half < 2; half++) {
            int m_local = warp_m*64 + mi*16 + half*8 + r4;
            int m = m0 + m_local;
            int b = m / T_;
            const float* qp = g_q + (size_t)b*E_ + n0;
            float partial = 0.f;
            #pragma unroll
            for (int ni = 0; ni < 4; ni++) {
                #pragma unroll
                for (int c = 0; c < 2; c++) {
                    int nl = warp_n*32 + ni*8 + cp2 + c;
                    float v = acc[mi][ni][half*2 + c] + qp[nl];
                    #pragma unroll
                    for (int o = 0; o < NF_; o++) v += f_s[m_local][o] * wfe_s[o][nl];
                    partial += fast_tanh(v) * wee_s[nl];
                }
            }
            partial += __shfl_xor_sync(0xffffffffu, partial, 1);
            partial += __shfl_xor_sync(0xffffffffu, partial, 2);
            if ((lane & 3) == 0) ep_s[m_local][warp_n] = partial;
        }
    }
    __syncthreads();
    if (tid < BM) {
        float ssum = ep_s[tid][0] + ep_s[tid][1] + ep_s[tid][2] + ep_s[tid][3];
        g_epart[(size_t)(m0 + tid)*NB_ + nb] = ssum;
    }
}

// ---------------------------------------------------------------------------
// softmax over T per batch (1024 threads)
// ---------------------------------------------------------------------------
__global__ void k_softmax(float* __restrict__ alpha_out) {
    int b = blockIdx.x;
    int tid = threadIdx.x;
    __shared__ float es[T_];
    __shared__ float red[1024];

    float lmax = -1e30f;
    for (int t = tid; t < T_; t += 1024) {
        float v = 0.f;
        #pragma unroll
        for (int nb = 0; nb < NB_; nb++) v += g_epart[(size_t)(b*T_ + t)*NB_ + nb];
        es[t] = v;
        lmax = fmaxf(lmax, v);
    }
    red[tid] = lmax;
    __syncthreads();
    for (int s = 512; s > 0; s >>= 1) {
        if (tid < s) red[tid] = fmaxf(red[tid], red[tid + s]);
        __syncthreads();
    }
    float mx = red[0];
    __syncthreads();

    float lsum = 0.f;
    for (int t = tid; t < T_; t += 1024) {
        float ev = expf(es[t] - mx);
        es[t] = ev;
        lsum += ev;
    }
    red[tid] = lsum;
    __syncthreads();
    for (int s = 512; s > 0; s >>= 1) {
        if (tid < s) red[tid] += red[tid + s];
        __syncthreads();
    }
    float inv = 1.f / red[0];
    __syncthreads();
    for (int t = tid; t < T_; t += 1024) alpha_out[b*T_ + t] = es[t] * inv;
}

// ---------------------------------------------------------------------------
// context g: 320 threads, uint4 (8 halves) per thread, 4 t-rows in flight.
// grid (B, 1, GZ=20); t-chunk = 100; thread sub = tid/80 covers t%4 slice.
// 80 deterministic partial slices total (GZ*4).
// ---------------------------------------------------------------------------
__global__ void __launch_bounds__(320) k_gpart(const float* __restrict__ alpha_out) {
    int b = blockIdx.x, z = blockIdx.z;
    int sub = threadIdx.x / 80;             // 0..3: t-phase
    int col = threadIdx.x % 80;             // uint4 column (8 halves)
    int t0 = z * (T_/GZ) + sub;
    const uint4* hp = reinterpret_cast<const uint4*>(g_Ah + (size_t)b*T_*E_) + col;
    const float* ap = alpha_out + b*T_;

    float acc[8];
    #pragma unroll
    for (int j = 0; j < 8; j++) acc[j] = 0.f;

    #pragma unroll 5
    for (int i = 0; i < (T_/GZ)/4; i++) {   // 25 iters
        int t = t0 + i*4;
        uint4 v = __ldg(hp + (size_t)t*(E_/8));
        float a = __ldg(ap + t);
        const __half2* h2 = reinterpret_cast<const __half2*>(&v);
        #pragma unroll
        for (int j = 0; j < 4; j++) {
            float2 f = __half22float2(h2[j]);
            acc[2*j]   += a * f.x;
            acc[2*j+1] += a * f.y;
        }
    }
    float* gp = g_gpart + ((size_t)(z*4 + sub)*B_ + b)*E_ + col*8;
    #pragma unroll
    for (int j = 0; j < 8; j++) gp[j] = acc[j];
}

__global__ void k_greduce(float* __restrict__ g_out) {
    int i = blockIdx.x*256 + threadIdx.x;
    if (i < B_*E_) {
        float s = 0.f;
        #pragma unroll
        for (int z = 0; z < GZ*4; z++) s += g_gpart[(size_t)z*(B_*E_) + i];
        g_out[i] = s;
    }
}

// ---------------------------------------------------------------------------
extern "C" void kernel_launch(void* const* d_in, const int* in_sizes, int n_in,
                              void* d_out, int out_size) {
    const float* s      = (const float*)d_in[0];
    const float* hb     = (const float*)d_in[1];
    const float* alpha  = (const float*)d_in[2];
    const float* W_se   = (const float*)d_in[4];
    const float* b_se   = (const float*)d_in[5];
    const float* W_he   = (const float*)d_in[6];
    const float* b_he   = (const float*)d_in[7];
    const float* W_fe   = (const float*)d_in[8];
    const float* b_fe   = (const float*)d_in[9];
    const float* W_ee   = (const float*)d_in[10];
    const float* conv_w = (const float*)d_in[12];

    float* out       = (float*)d_out;
    float* g_out     = out;            // [B, E]
    float* alpha_out = out + B_*E_;    // [B, T]

    cudaFuncSetAttribute(k_energy, cudaFuncAttributeMaxDynamicSharedMemorySize, NST*32768);

    k_prep<<<12144, 256>>>(hb, W_he, s, W_se, b_se, b_he, b_fe, alpha, conv_w);
    k_energy<<<dim3(NB_, M_/BM), 256, NST*32768>>>(W_fe, W_ee);
    k_softmax<<<B_, 1024>>>(alpha_out);
    k_gpart<<<dim3(B_, 1, GZ), 320>>>(alpha_out);
    k_greduce<<<(B_*E_ + 255)/256, 256>>>(g_out);
}